// round 3
// baseline (speedup 1.0000x reference)
#include <cuda_runtime.h>
#include <cuda_bf16.h>

// B = 8192 rows, T = 4096 features, G = 64 groups.
// Group sizes cycle (32, 64, 96, 64) x 16; all boundaries are multiples of 32,
// so each aligned 32-elem chunk belongs to exactly one group (128 chunks/row).
//
// Output: d_out[0..B) = Z (fp32), d_out[B..B+B*64) = a (fp32 row-major [B,64]).
//
// R3: persistent single-wave kernel (grid=1024 < 148*7), 8 rows per CTA,
// double-buffered prefetch: next row's 4 LDG.128 are issued before the barrier
// and warp-0 epilogue, so DRAM pressure never drops between rows. Ping-pong
// chunk_sum buffers -> one __syncthreads per row.

#define T_DIM     4096
#define G_DIM     64
#define NTHREADS  256
#define NBLOCKS   1024
#define ROWS_PER  8        // 8192 / 1024

__global__ __launch_bounds__(NTHREADS)
void agp_kernel(const float* __restrict__ H,
                const float* __restrict__ score_w,
                const float* __restrict__ score_b,
                float* __restrict__ out, int B)
{
    const int tid = threadIdx.x;
    const int row0 = blockIdx.x * ROWS_PER;

    __shared__ float chunk_sum[2][T_DIM / 32];   // ping-pong, 2 x 128
    __shared__ float s_w, s_b;
    if (tid == 0) { s_w = score_w[0]; s_b = score_b[0]; }

    // epilogue constants (warp 0 only uses them)
    const int   c_start[4] = {0, 1, 3, 6};
    const int   c_cnt[4]   = {1, 2, 3, 2};
    const float inv_sz[4]  = {1.0f/32.0f, 1.0f/64.0f, 1.0f/96.0f, 1.0f/64.0f};

    const float4* base4 = reinterpret_cast<const float4*>(H);

    // prefetch row 0
    float4 v[4];
    {
        const float4* r4 = base4 + (size_t)row0 * (T_DIM / 4);
        #pragma unroll
        for (int k = 0; k < 4; ++k)
            v[k] = r4[tid + NTHREADS * k];
    }

    int p = 0;
    #pragma unroll 1
    for (int it = 0; it < ROWS_PER; ++it) {
        const int b = row0 + it;

        // ---- reduce current row into chunk_sum[p] ----
        #pragma unroll
        for (int k = 0; k < 4; ++k) {
            float s = (v[k].x + v[k].y) + (v[k].z + v[k].w);
            s += __shfl_xor_sync(0xffffffffu, s, 1);
            s += __shfl_xor_sync(0xffffffffu, s, 2);
            s += __shfl_xor_sync(0xffffffffu, s, 4);
            if ((tid & 7) == 0)
                chunk_sum[p][(tid >> 3) + 32 * k] = s;
        }

        // ---- prefetch next row (clamped) BEFORE the barrier ----
        {
            int bn = (it + 1 < ROWS_PER) ? (b + 1) : b;   // clamp; last iter wasted but harmless
            const float4* r4 = base4 + (size_t)bn * (T_DIM / 4);
            #pragma unroll
            for (int k = 0; k < 4; ++k)
                v[k] = r4[tid + NTHREADS * k];
        }

        __syncthreads();

        // ---- warp 0: groups -> softmax -> Z for row b ----
        if (tid < 32) {
            const float w = s_w, bias = s_b;
            float Gm[2], sc[2];
            #pragma unroll
            for (int j = 0; j < 2; ++j) {
                int g    = tid + 32 * j;
                int sub  = g & 3;
                int base = (g >> 2) * 8 + c_start[sub];
                float s = 0.0f;
                #pragma unroll
                for (int c = 0; c < 3; ++c)
                    if (c < c_cnt[sub]) s += chunk_sum[p][base + c];
                Gm[j] = s * inv_sz[sub];
                sc[j] = Gm[j] * w + bias;
            }

            float mx = fmaxf(sc[0], sc[1]);
            #pragma unroll
            for (int d = 16; d > 0; d >>= 1)
                mx = fmaxf(mx, __shfl_xor_sync(0xffffffffu, mx, d));

            float p0 = expf(sc[0] - mx);
            float p1 = expf(sc[1] - mx);
            float ssum = p0 + p1;
            #pragma unroll
            for (int d = 16; d > 0; d >>= 1)
                ssum += __shfl_xor_sync(0xffffffffu, ssum, d);
            float inv = 1.0f / ssum;
            float a0 = p0 * inv;
            float a1 = p1 * inv;

            float zp = a0 * Gm[0] + a1 * Gm[1];
            #pragma unroll
            for (int d = 16; d > 0; d >>= 1)
                zp += __shfl_xor_sync(0xffffffffu, zp, d);

            float* a_out = out + B + (size_t)b * G_DIM;
            a_out[tid]      = a0;
            a_out[tid + 32] = a1;
            if (tid == 0) out[b] = zp;
        }

        p ^= 1;   // next row writes the other buffer; no second barrier needed
    }
}

extern "C" void kernel_launch(void* const* d_in, const int* in_sizes, int n_in,
                              void* d_out, int out_size)
{
    const float* H  = (const float*)d_in[0];   // [B, 4096]
    const float* sw = (const float*)d_in[1];   // [1,1]
    const float* sb = (const float*)d_in[2];   // [1]
    float* out = (float*)d_out;

    int B = in_sizes[0] / T_DIM;               // 8192
    agp_kernel<<<NBLOCKS, NTHREADS>>>(H, sw, sb, out, B);
}